// round 17
// baseline (speedup 1.0000x reference)
#include <cuda_runtime.h>
#include <cuda_fp16.h>
#include <cstdint>

// ---------------- problem constants ----------------
#define SEQ   2048
#define BH    32            // batch*heads
#define DDIM  128
#define TOKSTRIDE 4096      // BH*DDIM elements between consecutive tokens
#define NELEM (SEQ * TOKSTRIDE)

#define BM 64               // query rows per CTA (4 warps x m16)
#define BN 64               // kv rows per tile
#define NTILES (SEQ / BN)   // 32
#define NTHREADS 128

#define NUNITS 1024         // (qb, bh) work units
#define NFULL  888          // units run by one CTA (32 tiles)
#define NSPLIT 136          // units split into 2 CTAs (16 tiles each)
#define GRID   (NFULL + 2 * NSPLIT)   // 1160

#define QK_SCALE 0.08838834764831845f      // 1/sqrt(128)
#define L2E      1.4426950408889634f
#define ZSHIFT  (-11.541560327111707f)     // -8 * log2(e)

// smem: 2-stage double-buffered K and V tiles, [64 rows][272B] each
#define KROWB 272
#define TILEB 17408
#define SM_K0 0
#define SM_V0 (2 * TILEB)
#define SMEM_BYTES (4 * TILEB)

// ---------------- global scratch ----------------
__device__ __align__(256) __half g_k[NELEM];
__device__ __align__(256) __half g_v[NELEM];
__device__ float g_part_o[2 * NSPLIT][BM][DDIM];   // unnormalized partial O
__device__ float g_part_rs[2 * NSPLIT][BM];        // partial row sums
__device__ int   g_cnt[NSPLIT];                    // arrival counters

// ---------------- small helpers ----------------
__device__ __forceinline__ uint32_t smem_u32(const void* p) {
    uint32_t a;
    asm("{ .reg .u64 t; cvta.to.shared.u64 t, %1; cvt.u32.u64 %0, t; }" : "=r"(a) : "l"(p));
    return a;
}
__device__ __forceinline__ uint32_t packh2(float lo, float hi) {
    uint32_t r;
    asm("cvt.rn.f16x2.f32 %0, %1, %2;" : "=r"(r) : "f"(hi), "f"(lo));
    return r;
}
__device__ __forceinline__ void ldsm_x4(uint32_t* r, uint32_t addr) {
    asm volatile("ldmatrix.sync.aligned.m8n8.x4.shared.b16 {%0,%1,%2,%3}, [%4];"
                 : "=r"(r[0]), "=r"(r[1]), "=r"(r[2]), "=r"(r[3]) : "r"(addr));
}
__device__ __forceinline__ void ldsm_x4_t(uint32_t* r, uint32_t addr) {
    asm volatile("ldmatrix.sync.aligned.m8n8.x4.trans.shared.b16 {%0,%1,%2,%3}, [%4];"
                 : "=r"(r[0]), "=r"(r[1]), "=r"(r[2]), "=r"(r[3]) : "r"(addr));
}
__device__ __forceinline__ void mma_f16(float* d, const uint32_t* a, uint32_t b0, uint32_t b1) {
    asm volatile("mma.sync.aligned.m16n8k16.row.col.f32.f16.f16.f32 "
                 "{%0,%1,%2,%3}, {%4,%5,%6,%7}, {%8,%9}, {%0,%1,%2,%3};"
                 : "+f"(d[0]), "+f"(d[1]), "+f"(d[2]), "+f"(d[3])
                 : "r"(a[0]), "r"(a[1]), "r"(a[2]), "r"(a[3]), "r"(b0), "r"(b1));
}
#define CP16(dst, src) \
    asm volatile("cp.async.cg.shared.global [%0], [%1], 16;" :: "r"(dst), "l"(src) : "memory")
#define CP_COMMIT() asm volatile("cp.async.commit_group;" ::: "memory")
#define CP_WAIT(n)  asm volatile("cp.async.wait_group %0;" :: "n"(n) : "memory")

__device__ __forceinline__ float exp_mufu(float s) {
    float z = fmaf(s, L2E, ZSHIFT), r;
    asm("ex2.approx.f32 %0, %1;" : "=f"(r) : "f"(z));
    return r;
}

// ---------------- pre-pass: K/V fp32 -> fp16 ----------------
__global__ __launch_bounds__(256)
void prepass_kernel(const float* __restrict__ K, const float* __restrict__ V) {
    int i = blockIdx.x * blockDim.x + threadIdx.x;
    if (i >= NELEM / 2) return;
    float2 k = reinterpret_cast<const float2*>(K)[i];
    float2 v = reinterpret_cast<const float2*>(V)[i];
    reinterpret_cast<uint32_t*>(g_k)[i] = packh2(k.x, k.y);
    reinterpret_cast<uint32_t*>(g_v)[i] = packh2(v.x, v.y);
}

// ---------------- flag reset (every launch, graph-safe determinism) ----------------
__global__ void zero_flags_kernel() {
    if (threadIdx.x < NSPLIT) g_cnt[threadIdx.x] = 0;
}

// PV update for one 16-token kv chunk
__device__ __forceinline__ void pv_block(float (*o)[4], const uint32_t* pf,
                                         uint32_t vsb, int kc, uint32_t off_tr) {
    const uint32_t vbase = vsb + (uint32_t)(kc * 16 * KROWB) + off_tr;
    #pragma unroll
    for (int np = 0; np < 8; np++) {
        uint32_t v4[4];
        ldsm_x4_t(v4, vbase + np * 32);
        mma_f16(o[2 * np],     pf, v4[0], v4[1]);
        mma_f16(o[2 * np + 1], pf, v4[2], v4[3]);
    }
}

// ---------------- main attention kernel ----------------
__global__ __launch_bounds__(NTHREADS, 3)
void attn_hmma_kernel(const float* __restrict__ Q, float* __restrict__ Out) {
    extern __shared__ char smem[];
    __shared__ int s_old;
    const uint32_t sb = smem_u32(smem);

    const int bid = blockIdx.x;
    const int tid = threadIdx.x;
    const int wid = tid >> 5;
    const int lane = tid & 31;
    const int g = lane >> 2;
    const int j = lane & 3;

    // ---- work decomposition: full units vs split-KV tail units ----
    int unit, t0, t1, sidx;
    if (bid < NFULL) { unit = bid; t0 = 0; t1 = NTILES; sidx = -1; }
    else {
        const int s = bid - NFULL;           // 0..271
        unit = NFULL + (s >> 1);
        sidx = s;
        t0 = (s & 1) * (NTILES / 2);
        t1 = t0 + (NTILES / 2);
    }
    const int qb = unit & 31;
    const int bh = unit >> 5;

    const uint32_t off_nt = (uint32_t)((lane & 7) * KROWB + (lane >> 3) * 16);
    const uint32_t off_tr = (uint32_t)(((((lane >> 3) & 1) * 8) + (lane & 7)) * KROWB + (lane >> 4) * 16);

    // ---- stage Q: load fp32, scale+convert to fp16, through K-stage0 buffer ----
    uint32_t qf[8][4];
    {
        #pragma unroll
        for (int it = 0; it < 8; it++) {
            int idx = tid + it * NTHREADS;
            int row = idx >> 4, seg = idx & 15;
            const float* src = Q + (size_t)(qb * BM + row) * TOKSTRIDE + bh * DDIM + seg * 8;
            float4 a = *reinterpret_cast<const float4*>(src);
            float4 b = *reinterpret_cast<const float4*>(src + 4);
            uint4 h;
            h.x = packh2(a.x * QK_SCALE, a.y * QK_SCALE);
            h.y = packh2(a.z * QK_SCALE, a.w * QK_SCALE);
            h.z = packh2(b.x * QK_SCALE, b.y * QK_SCALE);
            h.w = packh2(b.z * QK_SCALE, b.w * QK_SCALE);
            *reinterpret_cast<uint4*>(smem + SM_K0 + row * KROWB + seg * 16) = h;
        }
        __syncthreads();
        const uint32_t abase = sb + SM_K0 + (uint32_t)(wid * 16 * KROWB) + off_tr;
        #pragma unroll
        for (int kc = 0; kc < 8; kc++) ldsm_x4(qf[kc], abase + kc * 32);
    }
    __syncthreads();

    float o[16][4];
    #pragma unroll
    for (int t = 0; t < 16; t++)
        #pragma unroll
        for (int v = 0; v < 4; v++) o[t][v] = 0.0f;
    float rs_lo = 0.0f, rs_hi = 0.0f;

    // ---- prologue: async-load tile t0 into stage (t0&1) ----
    {
        #pragma unroll
        for (int it = 0; it < 8; it++) {
            int idx = tid + it * NTHREADS;
            int row = idx >> 4, seg = idx & 15;
            size_t goff = (size_t)(t0 * BN + row) * TOKSTRIDE + bh * DDIM + seg * 8;
            uint32_t doff = (uint32_t)((t0 & 1) * TILEB + row * KROWB + seg * 16);
            CP16(sb + SM_K0 + doff, g_k + goff);
            CP16(sb + SM_V0 + doff, g_v + goff);
        }
        CP_COMMIT();
    }

    for (int kb = t0; kb < t1; kb++) {
        CP_WAIT(0);
        __syncthreads();

        if (kb + 1 < t1) {
            const int nxt = (kb + 1) & 1;
            #pragma unroll
            for (int it = 0; it < 8; it++) {
                int idx = tid + it * NTHREADS;
                int row = idx >> 4, seg = idx & 15;
                size_t goff = (size_t)((kb + 1) * BN + row) * TOKSTRIDE + bh * DDIM + seg * 8;
                uint32_t doff = (uint32_t)(nxt * TILEB + row * KROWB + seg * 16);
                CP16(sb + SM_K0 + doff, g_k + goff);
                CP16(sb + SM_V0 + doff, g_v + goff);
            }
            CP_COMMIT();
        }

        const uint32_t ksb = sb + SM_K0 + (uint32_t)((kb & 1) * TILEB);
        const uint32_t vsb = sb + SM_V0 + (uint32_t)((kb & 1) * TILEB);

        uint32_t pf_prev[4];
        #pragma unroll
        for (int kc = 0; kc < 4; kc++) {
            uint32_t kf[2][8][2];
            #pragma unroll
            for (int h = 0; h < 2; h++) {
                const uint32_t kbase = ksb + (uint32_t)((2 * kc + h) * 8 * KROWB) + off_nt;
                #pragma unroll
                for (int c = 0; c < 4; c++) {
                    uint32_t r4[4];
                    ldsm_x4(r4, kbase + c * 64);
                    kf[h][2 * c][0] = r4[0]; kf[h][2 * c][1] = r4[1];
                    kf[h][2 * c + 1][0] = r4[2]; kf[h][2 * c + 1][1] = r4[3];
                }
            }
            float s0[4] = {0.f, 0.f, 0.f, 0.f};
            float s1[4] = {0.f, 0.f, 0.f, 0.f};
            #pragma unroll
            for (int c = 0; c < 8; c++) {
                mma_f16(s0, qf[c], kf[0][c][0], kf[0][c][1]);
                mma_f16(s1, qf[c], kf[1][c][0], kf[1][c][1]);
            }

            if (kc > 0) pv_block(o, pf_prev, vsb, kc - 1, off_tr);

            float e0[4], e1[4];
            #pragma unroll
            for (int v = 0; v < 4; v++) { e0[v] = exp_mufu(s0[v]); e1[v] = exp_mufu(s1[v]); }
            rs_lo += e0[0] + e0[1] + e1[0] + e1[1];
            rs_hi += e0[2] + e0[3] + e1[2] + e1[3];
            pf_prev[0] = packh2(e0[0], e0[1]);
            pf_prev[1] = packh2(e0[2], e0[3]);
            pf_prev[2] = packh2(e1[0], e1[1]);
            pf_prev[3] = packh2(e1[2], e1[3]);
        }
        pv_block(o, pf_prev, vsb, 3, off_tr);
    }

    // ---- reduce row sums across the 4 j-lanes ----
    rs_lo += __shfl_xor_sync(0xffffffffu, rs_lo, 1);
    rs_lo += __shfl_xor_sync(0xffffffffu, rs_lo, 2);
    rs_hi += __shfl_xor_sync(0xffffffffu, rs_hi, 1);
    rs_hi += __shfl_xor_sync(0xffffffffu, rs_hi, 2);

    const int r0 = wid * 16 + g;        // local row (0..63), +8 for hi half
    const int row0 = qb * BM + r0;      // global token row

    if (sidx < 0) {
        // ---- full unit: normalize and store directly ----
        const float inv_lo = 1.0f / rs_lo;
        const float inv_hi = 1.0f / rs_hi;
        float* out0 = Out + (size_t)row0 * TOKSTRIDE + bh * DDIM;
        float* out1 = out0 + (size_t)8 * TOKSTRIDE;
        #pragma unroll
        for (int nt = 0; nt < 16; nt++) {
            const int col = nt * 8 + 2 * j;
            *reinterpret_cast<float2*>(out0 + col) = make_float2(o[nt][0] * inv_lo, o[nt][1] * inv_lo);
            *reinterpret_cast<float2*>(out1 + col) = make_float2(o[nt][2] * inv_hi, o[nt][3] * inv_hi);
        }
        return;
    }

    // ---- split unit: publish partial, second arriver combines ----
    {
        #pragma unroll
        for (int nt = 0; nt < 16; nt++) {
            const int col = nt * 8 + 2 * j;
            *reinterpret_cast<float2*>(&g_part_o[sidx][r0][col])     = make_float2(o[nt][0], o[nt][1]);
            *reinterpret_cast<float2*>(&g_part_o[sidx][r0 + 8][col]) = make_float2(o[nt][2], o[nt][3]);
        }
        if (j == 0) {
            g_part_rs[sidx][r0]     = rs_lo;
            g_part_rs[sidx][r0 + 8] = rs_hi;
        }
        __threadfence();
        __syncthreads();
        if (tid == 0) s_old = atomicAdd(&g_cnt[sidx >> 1], 1);
        __syncthreads();
        if (s_old == 0) return;      // first arriver: partner will combine
        __threadfence();             // acquire partner's stores

        const int partner = sidx ^ 1;
        const float inv_lo = 1.0f / (rs_lo + g_part_rs[partner][r0]);
        const float inv_hi = 1.0f / (rs_hi + g_part_rs[partner][r0 + 8]);
        float* out0 = Out + (size_t)row0 * TOKSTRIDE + bh * DDIM;
        float* out1 = out0 + (size_t)8 * TOKSTRIDE;
        #pragma unroll
        for (int nt = 0; nt < 16; nt++) {
            const int col = nt * 8 + 2 * j;
            float2 p0 = *reinterpret_cast<float2*>(&g_part_o[partner][r0][col]);
            float2 p1 = *reinterpret_cast<float2*>(&g_part_o[partner][r0 + 8][col]);
            *reinterpret_cast<float2*>(out0 + col) =
                make_float2((o[nt][0] + p0.x) * inv_lo, (o[nt][1] + p0.y) * inv_lo);
            *reinterpret_cast<float2*>(out1 + col) =
                make_float2((o[nt][2] + p1.x) * inv_hi, (o[nt][3] + p1.y) * inv_hi);
        }
    }
}

extern "C" void kernel_launch(void* const* d_in, const int* in_sizes, int n_in,
                              void* d_out, int out_size) {
    const float* Q = (const float*)d_in[0];
    const float* K = (const float*)d_in[1];
    const float* V = (const float*)d_in[2];
    float* Out = (float*)d_out;

    zero_flags_kernel<<<1, NSPLIT>>>();
    prepass_kernel<<<(NELEM / 2 + 255) / 256, 256>>>(K, V);

    cudaFuncSetAttribute(attn_hmma_kernel,
                         cudaFuncAttributeMaxDynamicSharedMemorySize, SMEM_BYTES);
    attn_hmma_kernel<<<GRID, NTHREADS, SMEM_BYTES>>>(Q, Out);
}